// round 14
// baseline (speedup 1.0000x reference)
#include <cuda_runtime.h>

#define B_    4
#define C_    64
#define P_    32768      // 128*256 pixels per batch
#define NC_   19
#define EPS_  1e-5f

// ---- stats kernel config ----
#define ST_TILE  2048
#define ST_THR   256
#define ST_RPT   8           // ST_TILE / ST_THR
#define ST_CHG   4           // channels per block
#define ST_TILES (P_ / ST_TILE)   // 16
#define ST_CG    (C_ / ST_CHG)    // 16 channel groups -> grid 1024

// ---- device scratch ----
__device__ unsigned char g_gtr[B_ * P_];        // subsampled class map (128 KB)
__device__ float2 g_acc[NC_ * B_ * C_];         // {sum, sumsq}
__device__ int    g_cnt[NC_ * B_];
__device__ float2 g_sb [NC_ * B_ * C_];         // {scale, bias}

// =============== kernel 1: stats (inline gt subsample + counting sort) ======
// Block = (b, pixel tile of 2048, group of 4 channels). Sort once, reuse for
// 4 channels. Each thread owns 8 contiguous sorted slots. Channel-invariant
// float masks tm[i] select the trailing run (rs/rq via FFMA); every
// non-trailing slot flushes individually with a predicated RED.64 (~90% of
// preds false; distinct classes -> no same-address replay). Trailing runs are
// merged across lanes by the warp segmented scan; tails flush. Branchless.
__global__ void __launch_bounds__(ST_THR) k_stats(const float* __restrict__ x,
                                                  const int*   __restrict__ gt) {
    __shared__ float s_vals[2][ST_TILE];
    __shared__ __align__(16) unsigned short s_order[ST_TILE]; // (class<<11)|pixel
    __shared__ int s_cnt[NC_];
    __shared__ int s_cur[NC_];

    const int tid  = threadIdx.x;
    const int bid  = blockIdx.x;                     // 1024 = b(4)*tile(16)*cg(16)
    const int b    = bid >> 8;
    const int tile = (bid >> 4) & 15;
    const int cg   = bid & 15;
    const int ch0  = cg * ST_CHG;
    const int lane = tid & 31;

    if (tid < NC_) s_cnt[tid] = 0;
    __syncthreads();

    // --- classify pixels of this tile (subsample gt on the fly) ---
    int cls[ST_RPT];
#pragma unroll
    for (int k = 0; k < ST_RPT; ++k) {
        int lp = tid + k * ST_THR;
        int p  = tile * ST_TILE + lp;
        int h  = p >> 8, w = p & 255;
        int c  = gt[(b << 19) + (h << 12) + (w << 2)];
        cls[k] = c;
        atomicAdd(&s_cnt[c], 1);
        if (cg == 0) g_gtr[b * P_ + p] = (unsigned char)c;   // for k_apply
    }
    __syncthreads();

    if (tid == 0) {
        int a = 0;
#pragma unroll
        for (int i = 0; i < NC_; ++i) { int n = s_cnt[i]; s_cur[i] = a; a += n; }
    }
    if (cg == 0 && tid < NC_) atomicAdd(&g_cnt[tid * B_ + b], s_cnt[tid]);
    __syncthreads();

    // --- scatter: build sorted order (ushort: class<<11 | local pixel) ---
#pragma unroll
    for (int k = 0; k < ST_RPT; ++k) {
        int lp  = tid + k * ST_THR;
        int pos = atomicAdd(&s_cur[cls[k]], 1);
        s_order[pos] = (unsigned short)((cls[k] << 11) | lp);
    }
    __syncthreads();

    // --- each thread caches its 8 contiguous sorted slots ---
    ushort4 oa = ((const ushort4*)s_order)[tid * 2];
    ushort4 ob = ((const ushort4*)s_order)[tid * 2 + 1];
    int c_[8], po[8];
    c_[0] = oa.x >> 11; po[0] = oa.x & 2047;
    c_[1] = oa.y >> 11; po[1] = oa.y & 2047;
    c_[2] = oa.z >> 11; po[2] = oa.z & 2047;
    c_[3] = oa.w >> 11; po[3] = oa.w & 2047;
    c_[4] = ob.x >> 11; po[4] = ob.x & 2047;
    c_[5] = ob.y >> 11; po[5] = ob.y & 2047;
    c_[6] = ob.z >> 11; po[6] = ob.z & 2047;
    c_[7] = ob.w >> 11; po[7] = ob.w & 2047;
    const int c7 = c_[7];

    // channel-invariant structure: trailing-run float masks + flush preds +
    // class offsets (classes non-decreasing => trailing run is a suffix)
    float tm[8];
    bool  fl[8];
    int   co[8];
    {
        bool t = true;
        tm[7] = 1.f; fl[7] = false; co[7] = c7 * (B_ * C_);
#pragma unroll
        for (int i = 6; i >= 0; --i) {
            t = t && (c_[i] == c7);
            tm[i] = t ? 1.f : 0.f;
            fl[i] = !t;
            co[i] = c_[i] * (B_ * C_);
        }
    }

    // hoisted segmented-scan structure (bitmask) + tail predicate
    unsigned tkm = 0;
#pragma unroll
    for (int d = 0; d < 5; ++d) {
        int sh = 1 << d;
        int oc = __shfl_up_sync(0xffffffffu, c7, sh);
        if ((lane >= sh) && (oc == c7)) tkm |= (1u << d);
    }
    const int  nxt  = __shfl_down_sync(0xffffffffu, c7, 1);
    const bool tail = (lane == 31) || (nxt != c7);

    // preload channel 0 tile (coalesced float4, 2 per thread)
    {
        const float4* xp = (const float4*)(x + ((size_t)(b * C_ + ch0)) * P_ + tile * ST_TILE);
        ((float4*)s_vals[0])[tid]          = xp[tid];
        ((float4*)s_vals[0])[tid + ST_THR] = xp[tid + ST_THR];
    }
    __syncthreads();

#pragma unroll
    for (int cc = 0; cc < ST_CHG; ++cc) {
        const int buf = cc & 1;
        float4 nva, nvb;
        const bool more = (cc + 1 < ST_CHG);
        if (more) {   // uniform branch; LDG issued early to hide latency
            const float4* xp = (const float4*)(x + ((size_t)(b * C_ + ch0 + cc + 1)) * P_ + tile * ST_TILE);
            nva = xp[tid];
            nvb = xp[tid + ST_THR];
        }

        float v[8], v2[8];
#pragma unroll
        for (int i = 0; i < 8; ++i) v[i]  = s_vals[buf][po[i]];
#pragma unroll
        for (int i = 0; i < 8; ++i) v2[i] = v[i] * v[i];

        // trailing-run sums via masked FFMA
        float rs = 0.f, rq = 0.f;
#pragma unroll
        for (int i = 0; i < 8; ++i) {
            rs = fmaf(tm[i], v[i],  rs);
            rq = fmaf(tm[i], v2[i], rq);
        }

        const int base = b * C_ + ch0 + cc;

        // per-slot predicated flush of non-trailing slots (rare, distinct classes)
#pragma unroll
        for (int i = 0; i < 8; ++i) {
            if (fl[i]) atomicAdd(&g_acc[co[i] + base], make_float2(v[i], v2[i]));
        }

        // warp segmented reduction of trailing partials (bitmask-gated)
#pragma unroll
        for (int d = 0; d < 5; ++d) {
            int sh = 1 << d;
            float os = __shfl_up_sync(0xffffffffu, rs, sh);
            float oq = __shfl_up_sync(0xffffffffu, rq, sh);
            bool tk = (tkm >> d) & 1u;
            rs += tk ? os : 0.f;
            rq += tk ? oq : 0.f;
        }
        if (tail) atomicAdd(&g_acc[co[7] + base], make_float2(rs, rq));

        if (more) {
            ((float4*)s_vals[buf ^ 1])[tid]          = nva;
            ((float4*)s_vals[buf ^ 1])[tid + ST_THR] = nvb;
        }
        __syncthreads();
    }
}

// =============== kernel 2: finalize affine params + reset accumulators ======
__global__ void __launch_bounds__(C_) k_finalize(const float* __restrict__ emu,
                                                 const float* __restrict__ estd) {
    const int c  = blockIdx.x;     // 0..18
    const int ch = threadIdx.x;    // 0..63

    float mean[B_], sd[B_];
#pragma unroll
    for (int b = 0; b < B_; ++b) {
        int   n   = g_cnt[c * B_ + b];
        float fn  = (n > 0) ? (float)n : 1.f;
        int   idx = (c * B_ + b) * C_ + ch;
        float2 a  = g_acc[idx];
        float m   = a.x / fn;
        float q   = a.y / fn;
        float var = fmaxf(q - m * m, 0.f);
        mean[b] = m;
        sd[b]   = sqrtf(var + EPS_);
    }
    float am = 0.25f * (mean[0] + mean[1] + mean[2] + mean[3]);
    float as = 0.25f * (sd[0] + sd[1] + sd[2] + sd[3]);
    float vm = 0.f, vs = 0.f;
#pragma unroll
    for (int b = 0; b < B_; ++b) {
        vm += (mean[b] - am) * (mean[b] - am);
        vs += (sd[b]   - as) * (sd[b]   - as);
    }
    vm *= (1.f / 3.f);   // ddof = 1, B = 4
    vs *= (1.f / 3.f);
    float sqm = sqrtf(vm + EPS_);
    float sqs = sqrtf(vs + EPS_);

#pragma unroll
    for (int b = 0; b < B_; ++b) {
        int   idx   = (c * B_ + b) * C_ + ch;
        float beta  = mean[b] + emu[idx]  * sqm;
        float gamma = sd[b]   + estd[idx] * sqs;
        float sc    = gamma / sd[b];
        g_sb[idx] = make_float2(sc, beta - mean[b] * sc);
    }

    // reset accumulators for the next graph replay (deterministic state)
    __syncthreads();
#pragma unroll
    for (int b = 0; b < B_; ++b) {
        g_acc[(c * B_ + b) * C_ + ch] = make_float2(0.f, 0.f);
    }
    if (ch < B_) g_cnt[c * B_ + ch] = 0;
}

// =============== kernel 3: apply out = x*scale[c] + bias[c] =================
// Table lives in warp registers (lane i holds entry i); lookup via shfl.idx.
__global__ void __launch_bounds__(256) k_apply(const float* __restrict__ x,
                                               float* __restrict__ out) {
    const int bid = blockIdx.x;          // 2048 = (4b*64ch)*8 splits
    const int s   = bid & 7;
    const int bc  = bid >> 3;            // b*64 + ch
    const int ch  = bc & 63;
    const int b   = bc >> 6;
    const int tid  = threadIdx.x;
    const int lane = tid & 31;

    float ssc = 0.f, sbi = 0.f;
    if (lane < NC_) {
        float2 t = g_sb[(lane * B_ + b) * C_ + ch];
        ssc = t.x; sbi = t.y;
    }

    const size_t base = ((size_t)bc) * P_ + s * 4096;
    const float4*   xp = (const float4*)(x + base);
    float4*         op = (float4*)(out + base);
    const unsigned* gp = (const unsigned*)(g_gtr + b * P_ + s * 4096);

#pragma unroll
    for (int j = 0; j < 4; ++j) {
        int i = tid + j * 256;
        float4   v = xp[i];
        unsigned u = gp[i];
        float4 r;
        {
            int c = u & 255u;
            r.x = fmaf(v.x, __shfl_sync(0xffffffffu, ssc, c),
                             __shfl_sync(0xffffffffu, sbi, c));
        }
        {
            int c = (u >> 8) & 255u;
            r.y = fmaf(v.y, __shfl_sync(0xffffffffu, ssc, c),
                             __shfl_sync(0xffffffffu, sbi, c));
        }
        {
            int c = (u >> 16) & 255u;
            r.z = fmaf(v.z, __shfl_sync(0xffffffffu, ssc, c),
                             __shfl_sync(0xffffffffu, sbi, c));
        }
        {
            int c = u >> 24;
            r.w = fmaf(v.w, __shfl_sync(0xffffffffu, ssc, c),
                             __shfl_sync(0xffffffffu, sbi, c));
        }
        __stcs(&op[i], r);   // streaming store: keep L2 for x
    }
}

// =============== launch ======================================================
extern "C" void kernel_launch(void* const* d_in, const int* in_sizes, int n_in,
                              void* d_out, int out_size) {
    const float* x    = (const float*)d_in[0];
    const int*   gt   = (const int*)  d_in[1];
    const float* emu  = (const float*)d_in[2];
    const float* estd = (const float*)d_in[3];
    float*       out  = (float*)d_out;

    k_stats   <<<B_ * ST_TILES * ST_CG, ST_THR>>>(x, gt);
    k_finalize<<<NC_, C_>>>(emu, estd);
    k_apply   <<<B_ * C_ * 8, 256>>>(x, out);
}

// round 15
// speedup vs baseline: 1.0767x; 1.0767x over previous
#include <cuda_runtime.h>

#define B_    4
#define C_    64
#define P_    32768      // 128*256 pixels per batch
#define NC_   19
#define EPS_  1e-5f

// ---- stats kernel config ----
#define ST_TILE  1024
#define ST_THR   256
#define ST_RPT   4           // ST_TILE / ST_THR
#define ST_CHG   8           // channels per block
#define ST_TILES 32          // P_ / ST_TILE
#define ST_CG    (C_ / ST_CHG)   // 8 channel groups -> grid 1024

// ---- device scratch ----
__device__ unsigned char g_gtr[B_ * P_];        // subsampled class map (128 KB)
__device__ float2 g_acc[NC_ * B_ * C_];         // {sum, sumsq}
__device__ int    g_cnt[NC_ * B_];
__device__ float2 g_sb [NC_ * B_ * C_];         // {scale, bias}

// =============== kernel 1: stats (inline gt subsample + counting sort) ======
// Block = (b, pixel tile of 1024, group of 8 channels). ALL 8 channel tiles
// are preloaded into separate smem buffers up front (LDG latency hidden by
// the sort); the channel loop then runs with ZERO barriers on read-only smem.
// Run merging: R6-proven select-chain trailing run + bool-predicate segmented
// scan; only segment tails / distinct heads / rare middles flush (float2
// RED.64). Same-address warp-wide flushes are forbidden (R4/R10 lesson).
__global__ void __launch_bounds__(ST_THR) k_stats(const float* __restrict__ x,
                                                  const int*   __restrict__ gt) {
    __shared__ float          s_vals[ST_CHG][ST_TILE];   // 32 KB
    __shared__ unsigned short s_order[ST_TILE];          // (class<<10) | pixel
    __shared__ int            s_cnt[NC_];
    __shared__ int            s_cur[NC_];

    const int tid  = threadIdx.x;
    const int bid  = blockIdx.x;                     // 1024 = b(4)*tile(32)*cg(8)
    const int b    = bid >> 8;
    const int tile = (bid >> 3) & 31;
    const int cg   = bid & 7;
    const int ch0  = cg * ST_CHG;
    const int lane = tid & 31;

    if (tid < NC_) s_cnt[tid] = 0;
    __syncthreads();

    // --- issue all 8 channel-tile loads NOW; sort work below hides latency ---
#pragma unroll
    for (int c = 0; c < ST_CHG; ++c) {
        const float4* xp = (const float4*)(x + ((size_t)(b * C_ + ch0 + c)) * P_
                                             + tile * ST_TILE);
        ((float4*)s_vals[c])[tid] = xp[tid];
    }

    // --- classify pixels of this tile (subsample gt on the fly) ---
    int cls[ST_RPT];
#pragma unroll
    for (int k = 0; k < ST_RPT; ++k) {
        int lp = tid + k * ST_THR;
        int p  = tile * ST_TILE + lp;
        int h  = p >> 8, w = p & 255;
        int c  = gt[(b << 19) + (h << 12) + (w << 2)];
        cls[k] = c;
        atomicAdd(&s_cnt[c], 1);
        if (cg == 0) g_gtr[b * P_ + p] = (unsigned char)c;   // for k_apply
    }
    __syncthreads();

    if (tid == 0) {
        int a = 0;
#pragma unroll
        for (int i = 0; i < NC_; ++i) { int n = s_cnt[i]; s_cur[i] = a; a += n; }
    }
    if (cg == 0 && tid < NC_) atomicAdd(&g_cnt[tid * B_ + b], s_cnt[tid]);
    __syncthreads();

    // --- scatter: build sorted order (ushort: class<<10 | local pixel) ---
#pragma unroll
    for (int k = 0; k < ST_RPT; ++k) {
        int lp  = tid + k * ST_THR;
        int pos = atomicAdd(&s_cur[cls[k]], 1);
        s_order[pos] = (unsigned short)((cls[k] << 10) | lp);
    }
    __syncthreads();   // orders the sort AND all 8 tile preloads

    // --- each thread caches its 4 contiguous sorted slots ---
    ushort4 o4 = ((const ushort4*)s_order)[tid];
    const int c0 = o4.x >> 10, c1 = o4.y >> 10, c2 = o4.z >> 10, c3 = o4.w >> 10;
    const int p0 = o4.x & 1023, p1 = o4.y & 1023, p2 = o4.z & 1023, p3 = o4.w & 1023;

    // run-membership predicates (classes non-decreasing => runs contiguous)
    const bool e23   = (c2 == c3);
    const bool e123  = e23 && (c1 == c2);
    const bool e0123 = e123 && (c0 == c1);
    const bool h1    = (c1 == c0);
    const bool h2    = (c2 == c0);
    const bool headp = (c0 != c3);
    const bool m1p   = (c1 != c0) && (c1 != c3);
    const bool m2p   = (c2 != c0) && (c2 != c3);

    // hoisted segmented-scan structure: bool predicates (NOT a bitmask —
    // bitmask unpacking per step regressed R11)
    bool take[5];
#pragma unroll
    for (int d = 0; d < 5; ++d) {
        int sh = 1 << d;
        int oc = __shfl_up_sync(0xffffffffu, c3, sh);
        take[d] = (lane >= sh) && (oc == c3);
    }
    const int  nxt  = __shfl_down_sync(0xffffffffu, c3, 1);
    const bool tail = (lane == 31) || (nxt != c3);

    // class offsets hoisted
    const int o0 = c0 * (B_ * C_);
    const int o1 = c1 * (B_ * C_);
    const int o2 = c2 * (B_ * C_);
    const int o3 = c3 * (B_ * C_);
    const int base0 = b * C_ + ch0;

    // --- channel loop: read-only smem, NO barriers ---
#pragma unroll
    for (int cc = 0; cc < ST_CHG; ++cc) {
        const float* sv = s_vals[cc];
        const float v0 = sv[p0];
        const float v1 = sv[p1];
        const float v2 = sv[p2];
        const float v3 = sv[p3];

        const int base = base0 + cc;

        // trailing run (class c3) — select-based, branch-free
        float rs = v3 + (e23 ? v2 : 0.f) + (e123 ? v1 : 0.f) + (e0123 ? v0 : 0.f);
        float rq = v3 * v3 + (e23 ? v2 * v2 : 0.f) + (e123 ? v1 * v1 : 0.f)
                 + (e0123 ? v0 * v0 : 0.f);

        // leading run (class c0) flushed when distinct from trailing (~7%)
        float hs = v0 + (h1 ? v1 : 0.f) + (h2 ? v2 : 0.f);
        float hq = v0 * v0 + (h1 ? v1 * v1 : 0.f) + (h2 ? v2 * v2 : 0.f);
        if (headp) atomicAdd(&g_acc[o0 + base], make_float2(hs, hq));

        // rare middle singleton runs (<1%)
        if (m1p) atomicAdd(&g_acc[o1 + base], make_float2(v1, v1 * v1));
        if (m2p) atomicAdd(&g_acc[o2 + base], make_float2(v2, v2 * v2));

        // warp segmented reduction of trailing partials (bool-gated)
#pragma unroll
        for (int d = 0; d < 5; ++d) {
            int sh = 1 << d;
            float os = __shfl_up_sync(0xffffffffu, rs, sh);
            float oq = __shfl_up_sync(0xffffffffu, rq, sh);
            rs += take[d] ? os : 0.f;
            rq += take[d] ? oq : 0.f;
        }
        if (tail) atomicAdd(&g_acc[o3 + base], make_float2(rs, rq));
    }
}

// =============== kernel 2: finalize affine params + reset accumulators ======
__global__ void __launch_bounds__(C_) k_finalize(const float* __restrict__ emu,
                                                 const float* __restrict__ estd) {
    const int c  = blockIdx.x;     // 0..18
    const int ch = threadIdx.x;    // 0..63

    float mean[B_], sd[B_];
#pragma unroll
    for (int b = 0; b < B_; ++b) {
        int   n   = g_cnt[c * B_ + b];
        float fn  = (n > 0) ? (float)n : 1.f;
        int   idx = (c * B_ + b) * C_ + ch;
        float2 a  = g_acc[idx];
        float m   = a.x / fn;
        float q   = a.y / fn;
        float var = fmaxf(q - m * m, 0.f);
        mean[b] = m;
        sd[b]   = sqrtf(var + EPS_);
    }
    float am = 0.25f * (mean[0] + mean[1] + mean[2] + mean[3]);
    float as = 0.25f * (sd[0] + sd[1] + sd[2] + sd[3]);
    float vm = 0.f, vs = 0.f;
#pragma unroll
    for (int b = 0; b < B_; ++b) {
        vm += (mean[b] - am) * (mean[b] - am);
        vs += (sd[b]   - as) * (sd[b]   - as);
    }
    vm *= (1.f / 3.f);   // ddof = 1, B = 4
    vs *= (1.f / 3.f);
    float sqm = sqrtf(vm + EPS_);
    float sqs = sqrtf(vs + EPS_);

#pragma unroll
    for (int b = 0; b < B_; ++b) {
        int   idx   = (c * B_ + b) * C_ + ch;
        float beta  = mean[b] + emu[idx]  * sqm;
        float gamma = sd[b]   + estd[idx] * sqs;
        float sc    = gamma / sd[b];
        g_sb[idx] = make_float2(sc, beta - mean[b] * sc);
    }

    // reset accumulators for the next graph replay (deterministic state)
    __syncthreads();
#pragma unroll
    for (int b = 0; b < B_; ++b) {
        g_acc[(c * B_ + b) * C_ + ch] = make_float2(0.f, 0.f);
    }
    if (ch < B_) g_cnt[c * B_ + ch] = 0;
}

// =============== kernel 3: apply out = x*scale[c] + bias[c] =================
// Table lives in warp registers (lane i holds entry i); lookup via shfl.idx.
__global__ void __launch_bounds__(256) k_apply(const float* __restrict__ x,
                                               float* __restrict__ out) {
    const int bid = blockIdx.x;          // 2048 = (4b*64ch)*8 splits
    const int s   = bid & 7;
    const int bc  = bid >> 3;            // b*64 + ch
    const int ch  = bc & 63;
    const int b   = bc >> 6;
    const int tid  = threadIdx.x;
    const int lane = tid & 31;

    float ssc = 0.f, sbi = 0.f;
    if (lane < NC_) {
        float2 t = g_sb[(lane * B_ + b) * C_ + ch];
        ssc = t.x; sbi = t.y;
    }

    const size_t base = ((size_t)bc) * P_ + s * 4096;
    const float4*   xp = (const float4*)(x + base);
    float4*         op = (float4*)(out + base);
    const unsigned* gp = (const unsigned*)(g_gtr + b * P_ + s * 4096);

#pragma unroll
    for (int j = 0; j < 4; ++j) {
        int i = tid + j * 256;
        float4   v = xp[i];
        unsigned u = gp[i];
        float4 r;
        {
            int c = u & 255u;
            r.x = fmaf(v.x, __shfl_sync(0xffffffffu, ssc, c),
                             __shfl_sync(0xffffffffu, sbi, c));
        }
        {
            int c = (u >> 8) & 255u;
            r.y = fmaf(v.y, __shfl_sync(0xffffffffu, ssc, c),
                             __shfl_sync(0xffffffffu, sbi, c));
        }
        {
            int c = (u >> 16) & 255u;
            r.z = fmaf(v.z, __shfl_sync(0xffffffffu, ssc, c),
                             __shfl_sync(0xffffffffu, sbi, c));
        }
        {
            int c = u >> 24;
            r.w = fmaf(v.w, __shfl_sync(0xffffffffu, ssc, c),
                             __shfl_sync(0xffffffffu, sbi, c));
        }
        __stcs(&op[i], r);   // streaming store: keep L2 for x
    }
}

// =============== launch ======================================================
extern "C" void kernel_launch(void* const* d_in, const int* in_sizes, int n_in,
                              void* d_out, int out_size) {
    const float* x    = (const float*)d_in[0];
    const int*   gt   = (const int*)  d_in[1];
    const float* emu  = (const float*)d_in[2];
    const float* estd = (const float*)d_in[3];
    float*       out  = (float*)d_out;

    k_stats   <<<B_ * ST_TILES * ST_CG, ST_THR>>>(x, gt);
    k_finalize<<<NC_, C_>>>(emu, estd);
    k_apply   <<<B_ * C_ * 8, 256>>>(x, out);
}